// round 13
// baseline (speedup 1.0000x reference)
#include <cuda_runtime.h>
#include <cuda_bf16.h>
#include <cstdint>

#define BATCH 16384
#define DIM   512
#define UNITS 1024
#define GAMMA 0.5f

// ---------------- device scratch (no cudaMalloc allowed; all overwrite-only) ----------------
__device__ float g_xsq[BATCH];
__device__ float g_musq_part[16][UNITS];        // per-32k-block partial ||mu_col||^2
__device__ __nv_bfloat16 g_xb[BATCH * DIM];     // x as bf16, [M][K]
__device__ __nv_bfloat16 g_mub[UNITS * DIM];    // mu transposed as bf16, [N][K]

// pack two floats -> bf16x2 as uint32
__device__ __forceinline__ uint32_t pack_bf2(float lo, float hi) {
    __nv_bfloat162 h = __floats2bfloat162_rn(lo, hi);
    __nv_bfloat162_raw r = *reinterpret_cast<__nv_bfloat162_raw*>(&h);
    return (uint32_t)r.x | ((uint32_t)r.y << 16);
}

// ---------------- merged prep kernel (measured-best) ----------------
__global__ __launch_bounds__(256)
void prep_kernel(const float* __restrict__ x, const float* __restrict__ mu) {
    if (blockIdx.x < 2048) {
        const int row  = blockIdx.x * 8 + threadIdx.y;
        const int lane = threadIdx.x;
        const float4* xr = reinterpret_cast<const float4*>(x + (size_t)row * DIM);
        uint2* dst = reinterpret_cast<uint2*>(g_xb + (size_t)row * DIM);
        float4 v0 = xr[lane];
        float4 v1 = xr[lane + 32];
        float4 v2 = xr[lane + 64];
        float4 v3 = xr[lane + 96];
        float s = v0.x*v0.x + v0.y*v0.y + v0.z*v0.z + v0.w*v0.w
                + v1.x*v1.x + v1.y*v1.y + v1.z*v1.z + v1.w*v1.w
                + v2.x*v2.x + v2.y*v2.y + v2.z*v2.z + v2.w*v2.w
                + v3.x*v3.x + v3.y*v3.y + v3.z*v3.z + v3.w*v3.w;
        dst[lane]      = make_uint2(pack_bf2(v0.x, v0.y), pack_bf2(v0.z, v0.w));
        dst[lane + 32] = make_uint2(pack_bf2(v1.x, v1.y), pack_bf2(v1.z, v1.w));
        dst[lane + 64] = make_uint2(pack_bf2(v2.x, v2.y), pack_bf2(v2.z, v2.w));
        dst[lane + 96] = make_uint2(pack_bf2(v3.x, v3.y), pack_bf2(v3.z, v3.w));
        #pragma unroll
        for (int o = 16; o > 0; o >>= 1) s += __shfl_xor_sync(0xffffffffu, s, o);
        if (lane == 0) g_xsq[row] = s;
    } else {
        __shared__ float t[32][33];
        __shared__ float ps[8][32];
        const int b = blockIdx.x - 2048;
        const int n0 = (b & 31) * 32, k0 = (b >> 5) * 32;
        const int tx = threadIdx.x, ty = threadIdx.y;
        for (int i = ty; i < 32; i += 8)
            t[i][tx] = mu[(size_t)(k0 + i) * UNITS + n0 + tx];
        __syncthreads();
        for (int i = ty; i < 32; i += 8)
            g_mub[(size_t)(n0 + i) * DIM + k0 + tx] = __float2bfloat16_rn(t[tx][i]);
        float s = 0.f;
        #pragma unroll
        for (int i = ty; i < 32; i += 8) { float v = t[i][tx]; s += v * v; }
        ps[ty][tx] = s;
        __syncthreads();
        if (ty == 0) {
            float tot = 0.f;
            #pragma unroll
            for (int j = 0; j < 8; j++) tot += ps[j][tx];
            g_musq_part[k0 >> 5][n0 + tx] = tot;
        }
    }
}

// ---------------- mma.sync GEMM, 2 M-tiles per CTA, fused RBF epilogue ----------------
#define BM 128
#define BN 128
#define BK 64
#define NIT2 16                 // 2 tiles x 8 K-iters, one fused pipeline
#define NSTAGE 3
#define A_SZ 16384              // 128 rows x 128B
#define B_SZ 16384
#define STAGE_BYTES (A_SZ + B_SZ)
#define MS_OFF (NSTAGE * STAGE_BYTES)           // musq tile region (512B)
#define SMEM_TOTAL (MS_OFF + 512)               // 96.5KB dynamic

__device__ __forceinline__ uint32_t smem_u32(const void* p) {
    uint32_t a;
    asm("{ .reg .u64 t; cvta.to.shared.u64 t, %1; cvt.u32.u64 %0, t; }" : "=r"(a) : "l"(p));
    return a;
}
__device__ __forceinline__ void cp16(uint32_t dst, const void* src) {
    asm volatile("cp.async.cg.shared.global [%0], [%1], 16;" :: "r"(dst), "l"(src));
}
__device__ __forceinline__ void ldm_x4(uint32_t& r0, uint32_t& r1, uint32_t& r2, uint32_t& r3,
                                       uint32_t addr) {
    asm volatile("ldmatrix.sync.aligned.m8n8.x4.shared.b16 {%0,%1,%2,%3}, [%4];"
                 : "=r"(r0), "=r"(r1), "=r"(r2), "=r"(r3) : "r"(addr));
}
__device__ __forceinline__ void mma16816(float* c, const uint32_t* a, const uint32_t* b) {
    asm volatile(
        "mma.sync.aligned.m16n8k16.row.col.f32.bf16.bf16.f32 "
        "{%0,%1,%2,%3}, {%4,%5,%6,%7}, {%8,%9}, {%0,%1,%2,%3};"
        : "+f"(c[0]), "+f"(c[1]), "+f"(c[2]), "+f"(c[3])
        : "r"(a[0]), "r"(a[1]), "r"(a[2]), "r"(a[3]), "r"(b[0]), "r"(b[1]));
}

// SW128 within a 128B row: chunk (16B) XOR row&7 -> conflict-free STS.128 + ldmatrix
__device__ __forceinline__ uint32_t off64(int row, int kc) {
    return ((uint32_t)row << 7) + ((uint32_t)((kc ^ (row & 7)) & 7) << 4);
}

__global__ __launch_bounds__(256, 2)
void rbf_mma_kernel(float* __restrict__ out) {
    extern __shared__ unsigned char sbuf[];

    const int tid  = threadIdx.x;
    const int lane = tid & 31, wid = tid >> 5;
    const int wm = wid >> 1, wn = wid & 1;          // warp grid 4 (M) x 2 (N); warp tile 32x64
    const int bx = blockIdx.x, byy = blockIdx.y;    // two M-tiles: rows byy*256 and +128

    const __nv_bfloat16* Ag0 = g_xb  + (size_t)(byy * 2 * BM) * DIM;
    const __nv_bfloat16* Ag1 = Ag0 + (size_t)BM * DIM;
    const __nv_bfloat16* Bg  = g_mub + (size_t)(bx * BN) * DIM;
    const uint32_t sbase = smem_u32(sbuf);

    float acc[2][8][4] = {};

    // fill stage buffer s with global pipeline step g (tile = g>>3, k0 = (g&7)*BK)
    #define STAGE_FILL(g)                                                            \
        {                                                                            \
            const __nv_bfloat16* Ap = ((g) < 8) ? Ag0 : Ag1;                         \
            const int k0 = ((g) & 7) * BK;                                           \
            const uint32_t ab = sbase + (uint32_t)((g) % NSTAGE) * STAGE_BYTES;      \
            const uint32_t bb = ab + A_SZ;                                           \
            _Pragma("unroll")                                                        \
            for (int i = 0; i < 4; i++) {                                            \
                const int linear = i * 256 + tid;                                    \
                const int row = linear >> 3, kc = linear & 7;                        \
                const uint32_t so = off64(row, kc);                                  \
                cp16(ab + so, Ap + (size_t)row * DIM + k0 + kc * 8);                 \
                cp16(bb + so, Bg + (size_t)row * DIM + k0 + kc * 8);                 \
            }                                                                        \
            asm volatile("cp.async.commit_group;");                                  \
        }

    #define STAGE_CONSUME(g)                                                         \
        {                                                                            \
            const uint32_t abuf = sbase + (uint32_t)((g) % NSTAGE) * STAGE_BYTES;    \
            const uint32_t bbuf = abuf + A_SZ;                                       \
            _Pragma("unroll")                                                        \
            for (int ks = 0; ks < 4; ks++) {                                         \
                uint32_t a[2][4], b[8][2];                                           \
                _Pragma("unroll")                                                    \
                for (int mt = 0; mt < 2; mt++)                                       \
                    ldm_x4(a[mt][0], a[mt][1], a[mt][2], a[mt][3],                   \
                           abuf + off64(wm * 32 + mt * 16 + (lane & 15),             \
                                        ks * 2 + ((lane >> 4) & 1)));                \
                _Pragma("unroll")                                                    \
                for (int np = 0; np < 4; np++) {                                     \
                    uint32_t r0, r1, r2, r3;                                         \
                    ldm_x4(r0, r1, r2, r3,                                           \
                           bbuf + off64(wn * 64 + np * 16 + (lane & 7)               \
                                        + ((lane & 16) ? 8 : 0),                     \
                                        ks * 2 + ((lane >> 3) & 1)));                \
                    b[np * 2][0] = r0; b[np * 2][1] = r1;                            \
                    b[np * 2 + 1][0] = r2; b[np * 2 + 1][1] = r3;                    \
                }                                                                    \
                _Pragma("unroll")                                                    \
                for (int mt = 0; mt < 2; mt++)                                       \
                    _Pragma("unroll")                                                \
                    for (int nt = 0; nt < 8; nt++)                                   \
                        mma16816(acc[mt][nt], a[mt], b[nt]);                         \
            }                                                                        \
        }

    #define EPILOGUE(tile_row_base)                                                  \
        {                                                                            \
            const int row0 = (tile_row_base) + wm * 32 + (lane >> 2);                \
            const int col0 = wn * 64 + (lane & 3) * 2;                               \
            _Pragma("unroll")                                                        \
            for (int mt = 0; mt < 2; mt++) {                                         \
                const int r = row0 + mt * 16;                                        \
                const float xs0 = g_xsq[r], xs1 = g_xsq[r + 8];                      \
                float* o0 = out + (size_t)r * UNITS + bx * BN;                       \
                float* o1 = out + (size_t)(r + 8) * UNITS + bx * BN;                 \
                _Pragma("unroll")                                                    \
                for (int nt = 0; nt < 8; nt++) {                                     \
                    const int c = col0 + nt * 8;                                     \
                    const float m0 = msm[c], m1 = msm[c + 1];                        \
                    float2 v0, v1;                                                   \
                    v0.x = __expf(-GAMMA * (xs0 - 2.f * acc[mt][nt][0] + m0));       \
                    v0.y = __expf(-GAMMA * (xs0 - 2.f * acc[mt][nt][1] + m1));       \
                    v1.x = __expf(-GAMMA * (xs1 - 2.f * acc[mt][nt][2] + m0));       \
                    v1.y = __expf(-GAMMA * (xs1 - 2.f * acc[mt][nt][3] + m1));       \
                    *reinterpret_cast<float2*>(o0 + c) = v0;                         \
                    *reinterpret_cast<float2*>(o1 + c) = v1;                         \
                }                                                                    \
            }                                                                        \
        }

    // prologue: steps 0,1 + musq combine (LDG latency hides under cp.async)
    STAGE_FILL(0)
    STAGE_FILL(1)
    float* msm = reinterpret_cast<float*>(sbuf + MS_OFF);
    if (tid < 128) {
        float s = 0.f;
        #pragma unroll
        for (int j = 0; j < 16; j++) s += g_musq_part[j][bx * BN + tid];
        msm[tid] = s;
    }

    // ---- tile 0: steps 0..7 ----
    #pragma unroll
    for (int g = 0; g < 8; g++) {
        asm volatile("cp.async.wait_group 1;");
        __syncthreads();
        STAGE_FILL(g + 2)       // g+2 <= 9 < 16 always valid here
        STAGE_CONSUME(g)
    }

    // tile0 epilogue overlaps tile1's in-flight cp.async fills (steps 8,9)
    EPILOGUE(byy * 2 * BM)
    #pragma unroll
    for (int mt = 0; mt < 2; mt++)
        #pragma unroll
        for (int nt = 0; nt < 8; nt++)
            #pragma unroll
            for (int q = 0; q < 4; q++) acc[mt][nt][q] = 0.f;

    // ---- tile 1: steps 8..15 ----
    #pragma unroll
    for (int g = 8; g < NIT2; g++) {
        if (g == NIT2 - 1) { asm volatile("cp.async.wait_group 0;"); }
        else               { asm volatile("cp.async.wait_group 1;"); }
        __syncthreads();
        if (g + 2 < NIT2) {
            STAGE_FILL(g + 2)
        }
        STAGE_CONSUME(g)
    }

    EPILOGUE(byy * 2 * BM + BM)
}

// ---------------- launch ----------------
extern "C" void kernel_launch(void* const* d_in, const int* in_sizes, int n_in,
                              void* d_out, int out_size) {
    const float* x  = (const float*)d_in[0];   // [16384, 512]
    const float* mu = (const float*)d_in[1];   // [512, 1024]
    float* out = (float*)d_out;                // [16384, 1024]

    cudaFuncSetAttribute(rbf_mma_kernel,
                         cudaFuncAttributeMaxDynamicSharedMemorySize, SMEM_TOTAL);

    prep_kernel<<<2048 + 512, dim3(32, 8)>>>(x, mu);

    dim3 grid(UNITS / BN, BATCH / (2 * BM));  // (8, 64) = 512 CTAs, 2 M-tiles each
    rbf_mma_kernel<<<grid, 256, SMEM_TOTAL>>>(out);
}

// round 16
// speedup vs baseline: 1.1708x; 1.1708x over previous
#include <cuda_runtime.h>
#include <cuda_bf16.h>
#include <cstdint>

#define BATCH 16384
#define DIM   512
#define UNITS 1024
#define GAMMA 0.5f

// ---------------- device scratch (no cudaMalloc allowed; all overwrite-only) ----------------
__device__ float g_xsq[BATCH];
__device__ float g_musq_part[16][UNITS];        // per-32k-block partial ||mu_col||^2
__device__ __nv_bfloat16 g_xb[BATCH * DIM];     // x as bf16, [M][K]
__device__ __nv_bfloat16 g_mub[UNITS * DIM];    // mu transposed as bf16, [N][K]

// pack two floats -> bf16x2 as uint32
__device__ __forceinline__ uint32_t pack_bf2(float lo, float hi) {
    __nv_bfloat162 h = __floats2bfloat162_rn(lo, hi);
    __nv_bfloat162_raw r = *reinterpret_cast<__nv_bfloat162_raw*>(&h);
    return (uint32_t)r.x | ((uint32_t)r.y << 16);
}

// ---------------- merged prep kernel (measured-best R10/R12 form) ----------------
// blocks [0, 2048): x -> bf16 + ||x_row||^2, 8 rows/block (warp per row), MLP=4
// blocks [2048, 2560): mu transpose 32x32 tile + partial col norms
__global__ __launch_bounds__(256)
void prep_kernel(const float* __restrict__ x, const float* __restrict__ mu) {
    if (blockIdx.x < 2048) {
        const int row  = blockIdx.x * 8 + threadIdx.y;
        const int lane = threadIdx.x;
        const float4* xr = reinterpret_cast<const float4*>(x + (size_t)row * DIM);
        uint2* dst = reinterpret_cast<uint2*>(g_xb + (size_t)row * DIM);
        float4 v0 = xr[lane];
        float4 v1 = xr[lane + 32];
        float4 v2 = xr[lane + 64];
        float4 v3 = xr[lane + 96];
        float s = v0.x*v0.x + v0.y*v0.y + v0.z*v0.z + v0.w*v0.w
                + v1.x*v1.x + v1.y*v1.y + v1.z*v1.z + v1.w*v1.w
                + v2.x*v2.x + v2.y*v2.y + v2.z*v2.z + v2.w*v2.w
                + v3.x*v3.x + v3.y*v3.y + v3.z*v3.z + v3.w*v3.w;
        dst[lane]      = make_uint2(pack_bf2(v0.x, v0.y), pack_bf2(v0.z, v0.w));
        dst[lane + 32] = make_uint2(pack_bf2(v1.x, v1.y), pack_bf2(v1.z, v1.w));
        dst[lane + 64] = make_uint2(pack_bf2(v2.x, v2.y), pack_bf2(v2.z, v2.w));
        dst[lane + 96] = make_uint2(pack_bf2(v3.x, v3.y), pack_bf2(v3.z, v3.w));
        #pragma unroll
        for (int o = 16; o > 0; o >>= 1) s += __shfl_xor_sync(0xffffffffu, s, o);
        if (lane == 0) g_xsq[row] = s;
    } else {
        __shared__ float t[32][33];
        __shared__ float ps[8][32];
        const int b = blockIdx.x - 2048;
        const int n0 = (b & 31) * 32, k0 = (b >> 5) * 32;
        const int tx = threadIdx.x, ty = threadIdx.y;
        for (int i = ty; i < 32; i += 8)
            t[i][tx] = mu[(size_t)(k0 + i) * UNITS + n0 + tx];
        __syncthreads();
        for (int i = ty; i < 32; i += 8)
            g_mub[(size_t)(n0 + i) * DIM + k0 + tx] = __float2bfloat16_rn(t[tx][i]);
        float s = 0.f;
        #pragma unroll
        for (int i = ty; i < 32; i += 8) { float v = t[i][tx]; s += v * v; }
        ps[ty][tx] = s;
        __syncthreads();
        if (ty == 0) {
            float tot = 0.f;
            #pragma unroll
            for (int j = 0; j < 8; j++) tot += ps[j][tx];
            g_musq_part[k0 >> 5][n0 + tx] = tot;
        }
    }
}

// ---------------- mma.sync GEMM + fused RBF epilogue ----------------
#define BM 128
#define BN 128
#define BK 64
#define NITER (DIM / BK)        // 8
#define NSTAGE 3
#define A_SZ 16384              // 128 rows x 128B
#define B_SZ 16384
#define STAGE_BYTES (A_SZ + B_SZ)
#define MS_OFF (NSTAGE * STAGE_BYTES)           // musq tile region (512B)
#define SMEM_TOTAL (MS_OFF + 512)               // 96.5KB dynamic

__device__ __forceinline__ uint32_t smem_u32(const void* p) {
    uint32_t a;
    asm("{ .reg .u64 t; cvta.to.shared.u64 t, %1; cvt.u32.u64 %0, t; }" : "=r"(a) : "l"(p));
    return a;
}
__device__ __forceinline__ void cp16(uint32_t dst, const void* src) {
    asm volatile("cp.async.cg.shared.global [%0], [%1], 16;" :: "r"(dst), "l"(src));
}
__device__ __forceinline__ void ldm_x4(uint32_t& r0, uint32_t& r1, uint32_t& r2, uint32_t& r3,
                                       uint32_t addr) {
    asm volatile("ldmatrix.sync.aligned.m8n8.x4.shared.b16 {%0,%1,%2,%3}, [%4];"
                 : "=r"(r0), "=r"(r1), "=r"(r2), "=r"(r3) : "r"(addr));
}
__device__ __forceinline__ void mma16816(float* c, const uint32_t* a, const uint32_t* b) {
    asm volatile(
        "mma.sync.aligned.m16n8k16.row.col.f32.bf16.bf16.f32 "
        "{%0,%1,%2,%3}, {%4,%5,%6,%7}, {%8,%9}, {%0,%1,%2,%3};"
        : "+f"(c[0]), "+f"(c[1]), "+f"(c[2]), "+f"(c[3])
        : "r"(a[0]), "r"(a[1]), "r"(a[2]), "r"(a[3]), "r"(b[0]), "r"(b[1]));
}

// SW128 within a 128B row: chunk (16B) XOR row&7 -> conflict-free STS.128 + ldmatrix
__device__ __forceinline__ uint32_t off64(int row, int kc) {
    return ((uint32_t)row << 7) + ((uint32_t)((kc ^ (row & 7)) & 7) << 4);
}

__global__ __launch_bounds__(256, 2)
void rbf_mma_kernel(float* __restrict__ out) {
    extern __shared__ unsigned char sbuf[];

    const int tid  = threadIdx.x;
    const int lane = tid & 31, wid = tid >> 5;
    const int wm = wid >> 1, wn = wid & 1;          // warp grid 4 (M) x 2 (N); warp tile 32x64
    const int bx = blockIdx.x, by = blockIdx.y;

    const __nv_bfloat16* Ag = g_xb  + (size_t)(by * BM) * DIM;
    const __nv_bfloat16* Bg = g_mub + (size_t)(bx * BN) * DIM;
    const uint32_t sbase = smem_u32(sbuf);

    float acc[2][8][4] = {};

    // per stage: A and B each 1024 x 16B transfers; 4 each per thread
    #define STAGE_FILL(s, k0)                                                        \
        {                                                                            \
            const uint32_t ab = sbase + (uint32_t)(s) * STAGE_BYTES;                 \
            const uint32_t bb = ab + A_SZ;                                           \
            _Pragma("unroll")                                                        \
            for (int i = 0; i < 4; i++) {                                            \
                const int linear = i * 256 + tid;                                    \
                const int row = linear >> 3, kc = linear & 7;                        \
                const uint32_t so = off64(row, kc);                                  \
                cp16(ab + so, Ag + (size_t)row * DIM + (k0) + kc * 8);               \
                cp16(bb + so, Bg + (size_t)row * DIM + (k0) + kc * 8);               \
            }                                                                        \
            asm volatile("cp.async.commit_group;");                                  \
        }

    // one k16 slice: ldmatrix A/B frags + 16 MMAs
    #define KS_CONSUME(abuf, bbuf, ks)                                               \
        {                                                                            \
            uint32_t a[2][4], b[8][2];                                               \
            _Pragma("unroll")                                                        \
            for (int mt = 0; mt < 2; mt++)                                           \
                ldm_x4(a[mt][0], a[mt][1], a[mt][2], a[mt][3],                       \
                       (abuf) + off64(wm * 32 + mt * 16 + (lane & 15),               \
                                      (ks) * 2 + ((lane >> 4) & 1)));                \
            _Pragma("unroll")                                                        \
            for (int np = 0; np < 4; np++) {                                         \
                uint32_t r0, r1, r2, r3;                                             \
                ldm_x4(r0, r1, r2, r3,                                               \
                       (bbuf) + off64(wn * 64 + np * 16 + (lane & 7)                 \
                                      + ((lane & 16) ? 8 : 0),                       \
                                      (ks) * 2 + ((lane >> 3) & 1)));                \
                b[np * 2][0] = r0; b[np * 2][1] = r1;                                \
                b[np * 2 + 1][0] = r2; b[np * 2 + 1][1] = r3;                        \
            }                                                                        \
            _Pragma("unroll")                                                        \
            for (int mt = 0; mt < 2; mt++)                                           \
                _Pragma("unroll")                                                    \
                for (int nt = 0; nt < 8; nt++)                                       \
                    mma16816(acc[mt][nt], a[mt], b[nt]);                             \
        }

    // prologue: stages 0,1 + musq combine (LDG latency hides under cp.async)
    STAGE_FILL(0, 0)
    STAGE_FILL(1, BK)
    float* msm = reinterpret_cast<float*>(sbuf + MS_OFF);
    if (tid < 128) {
        float s = 0.f;
        #pragma unroll
        for (int j = 0; j < 16; j++) s += g_musq_part[j][bx * BN + tid];
        msm[tid] = s;
    }

    #pragma unroll
    for (int it = 0; it < NITER; it++) {
        if (it == NITER - 1) { asm volatile("cp.async.wait_group 0;"); }
        else                 { asm volatile("cp.async.wait_group 1;"); }
        __syncthreads();

        const uint32_t abuf = sbase + (uint32_t)(it % NSTAGE) * STAGE_BYTES;
        const uint32_t bbuf = abuf + A_SZ;

        // start the tensor pipe immediately after the barrier...
        KS_CONSUME(abuf, bbuf, 0)
        // ...then issue next stage's fills under the remaining MMA work
        if (it + 2 < NITER) {
            STAGE_FILL((it + 2) % NSTAGE, (it + 2) * BK)
        }
        #pragma unroll
        for (int ks = 1; ks < 4; ks++) {
            KS_CONSUME(abuf, bbuf, ks)
        }
    }

    // ---- fused RBF epilogue (msm written pre-mainloop; visible via loop syncs) ----
    const int row0 = by * BM + wm * 32 + (lane >> 2);
    const int col0 = wn * 64 + (lane & 3) * 2;       // within CTA tile
    #pragma unroll
    for (int mt = 0; mt < 2; mt++) {
        const int r = row0 + mt * 16;
        const float xs0 = g_xsq[r], xs1 = g_xsq[r + 8];
        float* o0 = out + (size_t)r * UNITS + bx * BN;
        float* o1 = out + (size_t)(r + 8) * UNITS + bx * BN;
        #pragma unroll
        for (int nt = 0; nt < 8; nt++) {
            const int c = col0 + nt * 8;
            const float m0 = msm[c], m1 = msm[c + 1];
            float2 v0, v1;
            v0.x = __expf(-GAMMA * (xs0 - 2.f * acc[mt][nt][0] + m0));
            v0.y = __expf(-GAMMA * (xs0 - 2.f * acc[mt][nt][1] + m1));
            v1.x = __expf(-GAMMA * (xs1 - 2.f * acc[mt][nt][2] + m0));
            v1.y = __expf(-GAMMA * (xs1 - 2.f * acc[mt][nt][3] + m1));
            __stcs(reinterpret_cast<float2*>(o0 + c), v0);   // streaming: don't pollute L2
            __stcs(reinterpret_cast<float2*>(o1 + c), v1);
        }
    }
}

// ---------------- launch ----------------
extern "C" void kernel_launch(void* const* d_in, const int* in_sizes, int n_in,
                              void* d_out, int out_size) {
    const float* x  = (const float*)d_in[0];   // [16384, 512]
    const float* mu = (const float*)d_in[1];   // [512, 1024]
    float* out = (float*)d_out;                // [16384, 1024]

    cudaFuncSetAttribute(rbf_mma_kernel,
                         cudaFuncAttributeMaxDynamicSharedMemorySize, SMEM_TOTAL);

    prep_kernel<<<2048 + 512, dim3(32, 8)>>>(x, mu);

    dim3 grid(UNITS / BN, BATCH / BM);  // (8, 128) = 1024 CTAs
    rbf_mma_kernel<<<grid, 256, SMEM_TOTAL>>>(out);
}